// round 3
// baseline (speedup 1.0000x reference)
#include <cuda_runtime.h>

// ---------------------------------------------------------------------------
// SLUGenNet GCN, one persistent kernel, edge-parallel RED aggregation
// (no CSR at all).
//
//   P   = embed_table @ W1 + b1                       [V,32]   (phase A)
//   X1  = dinv[i] * P[nid[i]]                         [N,32]   (phase B)
//   H1[r] += X1[c]  over edges (r,c)                  RED      (phase C)
//   X2s = dinv[i] * (relu(dinv[i]*H1[i]) @ W2 + b2)   [N,32]   (phase D)
//   H2[r] += X2s[c] over edges                        RED      (phase E)
//   out = relu(dinv[i] * H2[i])                                (phase F)
//
// Grid barrier: monotonic generation counter (replay-safe, never reset).
// g_deg is re-zeroed in phase B; H1/H2 are re-zeroed in phase A.
// ---------------------------------------------------------------------------

#define N_NODES 12288
#define VOCAB   1000
#define EMBD    256
#define FEAT    32
#define NEDGE   (2 * N_NODES - 1)

#define GRID     128
#define NTHREADS 512
#define NWARPS   (NTHREADS / 32)          // 16
#define TOTWARPS (GRID * NWARPS)          // 2048
#define NPW      (N_NODES / TOTWARPS)     // 6 nodes per warp

// Scratch (__device__ globals; allocation-free rule). Zero-init at load.
__device__ int   g_deg[N_NODES];
__device__ float g_dinv[N_NODES];
__device__ float g_P [VOCAB * FEAT];
__device__ float g_X1[N_NODES * FEAT];
__device__ float g_X2[N_NODES * FEAT];
__device__ float g_H [2 * N_NODES * FEAT];   // H1 | H2 accumulators

// Grid barrier state: monotonic, never reset.
__device__ unsigned g_arrive;
__device__ volatile unsigned g_release;

__device__ __forceinline__ void gsync(unsigned gen) {
    __syncthreads();
    if (threadIdx.x == 0) {
        __threadfence();
        unsigned a = atomicAdd(&g_arrive, 1u) + 1u;
        if (a == gen * (unsigned)GRID) {
            g_release = gen;
        } else {
            while (g_release < gen) { }
        }
        __threadfence();
    }
    __syncthreads();
}

__global__ __launch_bounds__(NTHREADS, 1)
void slu_fused(const int*   __restrict__ nid,
               const int*   __restrict__ edges,
               const float* __restrict__ emb,
               const float* __restrict__ W1,
               const float* __restrict__ b1,
               const float* __restrict__ W2,
               const float* __restrict__ b2,
               float*       __restrict__ out) {
    __shared__ float s_buf[EMBD * FEAT];  // 32 KB: W1 tile; later W2 (4 KB)

    const int      t    = threadIdx.x;
    const unsigned lane = t & 31u;
    const int      warp = t >> 5;
    const int      b    = blockIdx.x;
    const int      gtid = b * NTHREADS + t;
    const int      gw   = b * NWARPS + warp;        // 0..2047

    float* __restrict__ H1 = g_H;
    float* __restrict__ H2 = g_H + N_NODES * FEAT;

    const unsigned base = g_release;      // stable since previous launch ended
    const int2* e2 = (const int2*)edges;

    // ======== phase A: zero accumulators + degree count + GEMM0 ===========
    {
        // zero H1|H2: 2*N*32 floats = 196608 float4 -> 3 per thread
        float4 z4 = make_float4(0.f, 0.f, 0.f, 0.f);
        float4* h4 = (float4*)g_H;
#pragma unroll
        for (int q = 0; q < (2 * N_NODES * FEAT / 4) / (GRID * NTHREADS); q++)
            h4[gtid + q * GRID * NTHREADS] = z4;

        // degree count (one edge per thread; 24575 < 65536)
        if (gtid < NEDGE) atomicAdd(&g_deg[e2[gtid].x], 1);

        // GEMM0 on blocks 0..31 (32 rows/block, 16 threads/row, 2 cols/thread)
        if (b < 32) {
            const float4* src = (const float4*)W1;
            float4*       dst = (float4*)s_buf;
#pragma unroll
            for (int q = 0; q < (EMBD * FEAT / 4) / NTHREADS; q++)
                dst[t + q * NTHREADS] = src[t + q * NTHREADS];
        }
        __syncthreads();
        if (b < 32) {
            int r  = b * 32 + (t >> 4);
            int c0 = (t & 15) * 2;
            if (r < VOCAB) {
                float a0 = b1[c0];
                float a1 = b1[c0 + 1];
                const float4* erow = (const float4*)(emb + (size_t)r * EMBD);
#pragma unroll 8
                for (int k4 = 0; k4 < EMBD / 4; k4++) {
                    float4 f = erow[k4];
                    const float fv[4] = {f.x, f.y, f.z, f.w};
#pragma unroll
                    for (int j = 0; j < 4; j++) {
                        int k = k4 * 4 + j;
                        float2 w = *(const float2*)&s_buf[k * FEAT + c0];
                        a0 = fmaf(fv[j], w.x, a0);
                        a1 = fmaf(fv[j], w.y, a1);
                    }
                }
                g_P[r * FEAT + c0]     = a0;
                g_P[r * FEAT + c0 + 1] = a1;
            }
        }
    }

    gsync(base + 1);

    // ======== phase B: dinv, deg reset, X1 = dinv * P[nid] ================
#pragma unroll
    for (int q = 0; q < NPW; q++) {
        int i = gw * NPW + q;
        int d = g_deg[i];                          // broadcast load
        float di = rsqrtf((float)d);
        if (lane == 0) { g_dinv[i] = di; g_deg[i] = 0; }
        int ni = nid[i];                           // broadcast load
        g_X1[i * FEAT + lane] = di * g_P[ni * FEAT + lane];
    }

    gsync(base + 2);

    // ======== phase C: H1[r] += X1[c] over edges (RED) =====================
#pragma unroll 4
    for (int e = gw; e < NEDGE; e += TOTWARPS) {
        int2 pc = e2[e];
        float v = g_X1[pc.y * FEAT + lane];
        atomicAdd(&H1[pc.x * FEAT + lane], v);
    }

    gsync(base + 3);

    // ======== phase D: h = relu(dinv*H1); X2s = dinv*(h@W2 + b2) ==========
    {
        if (t < FEAT * FEAT / 4)
            ((float4*)s_buf)[t] = ((const float4*)W2)[t];
        __syncthreads();
        const float b2v = b2[lane];
#pragma unroll
        for (int q = 0; q < NPW; q++) {
            int i = gw * NPW + q;
            float di = g_dinv[i];
            float h  = fmaxf(di * H1[i * FEAT + lane], 0.f);
            float x2 = b2v;
#pragma unroll
            for (int k = 0; k < FEAT; k++) {
                float hk = __shfl_sync(0xffffffffu, h, k);
                x2 = fmaf(hk, s_buf[k * FEAT + lane], x2);
            }
            g_X2[i * FEAT + lane] = di * x2;
        }
    }

    gsync(base + 4);

    // ======== phase E: H2[r] += X2s[c] over edges (RED) ====================
#pragma unroll 4
    for (int e = gw; e < NEDGE; e += TOTWARPS) {
        int2 pc = e2[e];
        float v = g_X2[pc.y * FEAT + lane];
        atomicAdd(&H2[pc.x * FEAT + lane], v);
    }

    gsync(base + 5);

    // ======== phase F: out = relu(dinv * H2) ===============================
#pragma unroll
    for (int q = 0; q < NPW; q++) {
        int i = gw * NPW + q;
        float di = g_dinv[i];
        out[i * FEAT + lane] = fmaxf(di * H2[i * FEAT + lane], 0.f);
    }
}

// ---------------------------------------------------------------------------
extern "C" void kernel_launch(void* const* d_in, const int* in_sizes, int n_in,
                              void* d_out, int out_size) {
    const int*   node_ids = (const int*)d_in[0];
    const int*   edges    = (const int*)d_in[1];
    const float* emb      = (const float*)d_in[2];
    const float* W1       = (const float*)d_in[3];
    const float* b1       = (const float*)d_in[4];
    const float* W2       = (const float*)d_in[5];
    const float* b2       = (const float*)d_in[6];
    float* out = (float*)d_out;

    slu_fused<<<GRID, NTHREADS>>>(node_ids, edges, emb, W1, b1, W2, b2, out);
}